// round 10
// baseline (speedup 1.0000x reference)
#include <cuda_runtime.h>
#include <cuda_fp16.h>
#include <cstdint>

#define BSZ   128
#define NNODE 4000
#define DF    128
#define NB    10
#define SEQ   400
#define C1    32
#define C2    32
#define MTILE 128
#define MTOT  (BSZ*SEQ)          // 51200
#define NCTA  (MTOT/MTILE)       // 400
#define NSTAGE 20                // NB * 2 half-K stages

// ---- shared memory byte layout (dynamic) ----------------------------------
#define SMB_IDX   0                         // 1280 ints = 5120 B
#define SMB_MBAR  5120                      // 2 x 8B mbarriers
#define SMB_A     5136                      // 2 x 34816 B (128 rows x 272 B)
#define A_ROW     272
#define A_STAGE   (MTILE*A_ROW)             // 34816
#define SMB_B     (SMB_A + 2*A_STAGE)       // 74768
#define B_STAGE   5120                      // 32 pair-rows x 160 B (pre-padded)
#define SMB_TOTAL (SMB_B + 2*B_STAGE)       // 85008 -> 2 CTAs/SM
#define STAGE_TX  (MTILE*256 + B_STAGE)     // 37888 bytes per stage

__device__ uint32_t g_w1h[NB*64*40];  // f16 pairs: [k][pair(d/2)][c1], 40-u32 rows
__device__ float    g_partial[MTOT];

__device__ __forceinline__ uint32_t smem_u32(const void* p) {
    uint32_t a;
    asm("{ .reg .u64 t; cvta.to.shared.u64 t, %1; cvt.u32.u64 %0, t; }" : "=r"(a) : "l"(p));
    return a;
}
#define MB_INIT(mb, c) \
    asm volatile("mbarrier.init.shared.b64 [%0], %1;" :: "r"(mb), "r"((uint32_t)(c)) : "memory")
#define MB_EXPECT_TX(mb, n) \
    asm volatile("mbarrier.arrive.expect_tx.shared.b64 _, [%0], %1;" \
                 :: "r"(mb), "r"((uint32_t)(n)) : "memory")
#define MB_WAIT(mb, ph) do { \
    uint32_t _m = (mb), _p = (ph), _d; \
    asm volatile("{\n\t.reg .pred p;\n\t" \
        "mbarrier.try_wait.parity.acquire.cta.shared::cta.b64 p, [%1], %2;\n\t" \
        "selp.b32 %0, 1, 0, p;\n\t}" : "=r"(_d) : "r"(_m), "r"(_p) : "memory"); \
    if (!_d) { asm volatile("{\n\t.reg .pred P1;\n\tW%=:\n\t" \
        "mbarrier.try_wait.parity.acquire.cta.shared::cta.b64 P1, [%0], %1, 0x989680;\n\t" \
        "@P1 bra.uni D%=;\n\tbra.uni W%=;\n\tD%=:\n\t}" :: "r"(_m), "r"(_p) : "memory"); } \
} while (0)
__device__ __forceinline__ void bulk_ld(uint32_t dst, const void* src,
                                        uint32_t bytes, uint32_t mbar) {
    asm volatile(
        "cp.async.bulk.shared::cluster.global.mbarrier::complete_tx::bytes "
        "[%0], [%1], %2, [%3];"
        :: "r"(dst), "l"(src), "r"(bytes), "r"(mbar) : "memory");
}

__device__ __forceinline__ uint32_t packh2(float2 v) {
    uint32_t r;
    asm("cvt.rn.f16x2.f32 %0, %1, %2;" : "=r"(r) : "f"(v.y), "f"(v.x));
    return r;
}
__device__ __forceinline__ void mma16816(float* c, uint32_t a0, uint32_t a1,
                                         uint32_t a2, uint32_t a3,
                                         uint32_t b0, uint32_t b1) {
    asm volatile(
        "mma.sync.aligned.m16n8k16.row.col.f32.f16.f16.f32 "
        "{%0,%1,%2,%3}, {%4,%5,%6,%7}, {%8,%9}, {%0,%1,%2,%3};"
        : "+f"(c[0]), "+f"(c[1]), "+f"(c[2]), "+f"(c[3])
        : "r"(a0), "r"(a1), "r"(a2), "r"(a3), "r"(b0), "r"(b1));
}

// ---------------------------------------------------------------------------
// prep: conv1 weights -> f16 pair-interleaved [k][d/2][c1] rows (40 u32 pad)
// ---------------------------------------------------------------------------
__global__ void prep_kernel(const float* __restrict__ w1) {
    int i = blockIdx.x * blockDim.x + threadIdx.x;     // 40960
    if (i >= NB * DF * C1) return;
    int k   = i >> 12;
    int rem = i & 4095;
    int d   = rem >> 5;
    int c1  = rem & 31;
    float v = w1[c1 * (DF * NB) + d * NB + k];
    ((__half*)g_w1h)[((size_t)k * 2560 + (d >> 1) * 40 + c1) * 2 + (d & 1)] =
        __float2half_rn(v);
}

// ---------------------------------------------------------------------------
// fused: TMA-bulk-gathered, mbarrier-pipelined f16 mma conv1 + relu + conv2
//        + relu + FC partial
// ---------------------------------------------------------------------------
__global__ __launch_bounds__(256, 2) void conv_kernel(
    const int*   __restrict__ recep,
    const float* __restrict__ nf,
    const float* __restrict__ b1,
    const float* __restrict__ w2,
    const float* __restrict__ b2,
    const float* __restrict__ fcw)
{
    extern __shared__ char smem[];
    const uint32_t sbase = smem_u32(smem);
    int* sIdx = (int*)(smem + SMB_IDX);
    const int tid  = threadIdx.x;
    const int wid  = tid >> 5;
    const int lane = tid & 31;
    const int m0   = blockIdx.x * MTILE;
    const int fr   = lane >> 2;      // 0..7
    const int fc   = lane & 3;       // 0..3
    const uint32_t fb[2] = { sbase + SMB_MBAR, sbase + SMB_MBAR + 8 };

    // node index table: 128 rows x 10 neighbors
    for (int i = tid; i < MTILE * NB; i += 256) {
        int row = i / NB;
        int k   = i - row * NB;
        int m   = m0 + row;
        int b   = m / SEQ;
        int s   = m - b * SEQ;
        sIdx[i] = recep[b * NNODE + s * NB + k] + b * NNODE;
    }
    if (tid == 0) { MB_INIT(fb[0], 1); MB_INIT(fb[1], 1); }
    __syncthreads();

    // warp-0-only: issue one stage of bulk copies (A: 128 x 256B, B: 1 x 5120B)
    auto prefetch = [&](int s) {
        const int k = s >> 1, h = s & 1, bi = s & 1;
        if (lane == 0) MB_EXPECT_TX(fb[bi], STAGE_TX);
        __syncwarp();
        uint32_t abase = sbase + SMB_A + bi * A_STAGE;
#pragma unroll
        for (int j = 0; j < 4; j++) {
            int row  = lane + j * 32;
            int node = sIdx[row * NB + k];
            bulk_ld(abase + (uint32_t)row * A_ROW,
                    nf + (size_t)node * DF + h * 64, 256, fb[bi]);
        }
        if (lane == 0)
            bulk_ld(sbase + SMB_B + bi * B_STAGE,
                    (const char*)g_w1h + (size_t)k * 10240 + h * B_STAGE,
                    B_STAGE, fb[bi]);
    };

    if (wid == 0) { prefetch(0); prefetch(1); }

    float acc[4][4];
#pragma unroll
    for (int nt = 0; nt < 4; nt++)
#pragma unroll
        for (int j = 0; j < 4; j++) acc[nt][j] = 0.f;

    const int row0 = wid * 16 + fr;

    for (int s = 0; s < NSTAGE; s++) {
        const int bi = s & 1;
        MB_WAIT(fb[bi], (s >> 1) & 1);

        const float*    aw = (const float*)(smem + SMB_A + bi * A_STAGE);
        const uint32_t* bw = (const uint32_t*)(smem + SMB_B + bi * B_STAGE);
#pragma unroll
        for (int t = 0; t < 4; t++) {
            const int c0 = 16 * t + 2 * fc;            // float col of first pair
            const float* r0 = aw + row0 * 68;          // 272B rows = 68 floats
            const float* r1 = aw + (row0 + 8) * 68;
            float2 v00 = *(const float2*)(r0 + c0);
            float2 v10 = *(const float2*)(r1 + c0);
            float2 v01 = *(const float2*)(r0 + c0 + 8);
            float2 v11 = *(const float2*)(r1 + c0 + 8);
            uint32_t a0 = packh2(v00), a1 = packh2(v10);
            uint32_t a2 = packh2(v01), a3 = packh2(v11);
            const int p0 = (8 * t + fc) * 40;          // k = 16t+2fc,+1
            const int p1 = (8 * t + 4 + fc) * 40;      // k = 16t+8+2fc,+1
#pragma unroll
            for (int nt = 0; nt < 4; nt++) {
                uint32_t b0 = bw[p0 + nt * 8 + fr];
                uint32_t b1v = bw[p1 + nt * 8 + fr];
                mma16816(acc[nt], a0, a1, a2, a3, b0, b1v);
            }
        }
        __syncthreads();                            // all readers done with bi
        if (wid == 0 && s + 2 < NSTAGE) prefetch(s + 2);
    }

    // y1 = relu(conv1 + b1) -> smem [128][33]; w2 -> smem
    float* y1s = (float*)(smem + SMB_A);
    float* w2s = (float*)(smem + SMB_B);
    const int rb = wid * 16;
#pragma unroll
    for (int nt = 0; nt < 4; nt++) {
        int col = nt * 8 + 2 * fc;
        float bc0 = __ldg(b1 + col), bc1 = __ldg(b1 + col + 1);
        y1s[(rb + fr)     * 33 + col]     = fmaxf(acc[nt][0] + bc0, 0.f);
        y1s[(rb + fr)     * 33 + col + 1] = fmaxf(acc[nt][1] + bc1, 0.f);
        y1s[(rb + fr + 8) * 33 + col]     = fmaxf(acc[nt][2] + bc0, 0.f);
        y1s[(rb + fr + 8) * 33 + col + 1] = fmaxf(acc[nt][3] + bc1, 0.f);
    }
    ((float4*)w2s)[tid] = ((const float4*)w2)[tid & 255];
    __syncthreads();

    // conv2 (fp32) + relu + FC partial: one thread per row
    if (tid < MTILE) {
        int m = m0 + tid;
        int b = m / SEQ;
        int s = m - b * SEQ;
        const float* yr = y1s + tid * 33;
        float p = 0.f;
#pragma unroll
        for (int c2 = 0; c2 < C2; c2++) {
            float v = __ldg(b2 + c2);
            const float* wv = w2s + c2 * 32;
#pragma unroll
            for (int q = 0; q < 32; q += 4) {
                v = fmaf(wv[q],     yr[q],     v);
                v = fmaf(wv[q + 1], yr[q + 1], v);
                v = fmaf(wv[q + 2], yr[q + 2], v);
                v = fmaf(wv[q + 3], yr[q + 3], v);
            }
            v = fmaxf(v, 0.f);
            p = fmaf(v, __ldg(fcw + c2 * SEQ + s), p);
        }
        g_partial[m] = p;
    }
}

// ---------------------------------------------------------------------------
__global__ void reduce_kernel(const float* __restrict__ fcb, float* __restrict__ out) {
    __shared__ float red[128];
    int b = blockIdx.x, tid = threadIdx.x;
    float s = 0.f;
    for (int i = tid; i < SEQ; i += 128) s += g_partial[b * SEQ + i];
    red[tid] = s;
    __syncthreads();
    for (int st = 64; st > 0; st >>= 1) {
        if (tid < st) red[tid] += red[tid + st];
        __syncthreads();
    }
    if (tid == 0) out[b] = red[0] + fcb[0];
}

// ---------------------------------------------------------------------------
extern "C" void kernel_launch(void* const* d_in, const int* in_sizes, int n_in,
                              void* d_out, int out_size) {
    const int*   recep = (const int*)  d_in[0];
    const float* nf    = (const float*)d_in[1];
    const float* w1    = (const float*)d_in[2];
    const float* b1    = (const float*)d_in[3];
    const float* w2    = (const float*)d_in[4];
    const float* b2    = (const float*)d_in[5];
    const float* fcw   = (const float*)d_in[6];
    const float* fcb   = (const float*)d_in[7];
    float* out = (float*)d_out;

    cudaFuncSetAttribute(conv_kernel, cudaFuncAttributeMaxDynamicSharedMemorySize, SMB_TOTAL);
    prep_kernel<<<(NB*DF*C1 + 255) / 256, 256>>>(w1);
    conv_kernel<<<NCTA, 256, SMB_TOTAL>>>(recep, nf, b1, w2, b2, fcw);
    reduce_kernel<<<BSZ, 128>>>(fcb, out);
}

// round 11
// speedup vs baseline: 1.1276x; 1.1276x over previous
#include <cuda_runtime.h>
#include <cuda_fp16.h>
#include <cstdint>

#define BSZ   128
#define NNODE 4000
#define DF    128
#define NB    10
#define SEQ   400
#define C1    32
#define C2    32
#define MTILE 128
#define MTOT  (BSZ*SEQ)          // 51200
#define NCTA  (MTOT/MTILE)       // 400
#define NSTAGE 20                // NB * 2 half-K stages

// ---- shared memory byte layout (dynamic) ----------------------------------
#define SMB_IDX   0                         // 1280 ints (byte offsets) = 5120 B
#define SMB_A     5120                      // 2 x 32 KB fp32 half-K stages
#define A_STAGE   (MTILE*64*4)              // 32768
#define SMB_TOTAL (SMB_A + 2*A_STAGE)       // 70656 -> 2 CTAs/SM

__device__ uint32_t g_w1h[NB*64*32];  // dense f16 pairs: [k][pair(d/2)][c1]
__device__ float    g_partial[MTOT];
__device__ int      g_cnt[BSZ];       // zero-init; self-resetting per call

__device__ __forceinline__ uint32_t smem_u32(const void* p) {
    uint32_t a;
    asm("{ .reg .u64 t; cvta.to.shared.u64 t, %1; cvt.u32.u64 %0, t; }" : "=r"(a) : "l"(p));
    return a;
}
__device__ __forceinline__ void cp16(uint32_t dst, const void* src) {
    asm volatile("cp.async.cg.shared.global [%0], [%1], 16;" :: "r"(dst), "l"(src));
}
#define CP_COMMIT() asm volatile("cp.async.commit_group;" ::: "memory")
#define CP_WAIT(N)  asm volatile("cp.async.wait_group %0;" :: "n"(N) : "memory")

__device__ __forceinline__ uint32_t packh2(float2 v) {
    uint32_t r;
    asm("cvt.rn.f16x2.f32 %0, %1, %2;" : "=r"(r) : "f"(v.y), "f"(v.x));
    return r;
}
__device__ __forceinline__ void mma16816(float* c, uint32_t a0, uint32_t a1,
                                         uint32_t a2, uint32_t a3,
                                         uint32_t b0, uint32_t b1) {
    asm volatile(
        "mma.sync.aligned.m16n8k16.row.col.f32.f16.f16.f32 "
        "{%0,%1,%2,%3}, {%4,%5,%6,%7}, {%8,%9}, {%0,%1,%2,%3};"
        : "+f"(c[0]), "+f"(c[1]), "+f"(c[2]), "+f"(c[3])
        : "r"(a0), "r"(a1), "r"(a2), "r"(a3), "r"(b0), "r"(b1));
}

// ---------------------------------------------------------------------------
// prep: conv1 weights -> dense f16 pair-interleaved [k][d/2][c1]
// ---------------------------------------------------------------------------
__global__ void prep_kernel(const float* __restrict__ w1) {
    int i = blockIdx.x * blockDim.x + threadIdx.x;     // 40960
    if (i >= NB * DF * C1) return;
    int k   = i >> 12;
    int rem = i & 4095;
    int d   = rem >> 5;
    int c1  = rem & 31;
    float v = w1[c1 * (DF * NB) + d * NB + k];
    ((__half*)g_w1h)[((size_t)k * 2048 + (d >> 1) * 32 + c1) * 2 + (d & 1)] =
        __float2half_rn(v);
}

// ---------------------------------------------------------------------------
// fused: lean cp.async pipeline + f16 mma conv1 (B via L1 ldg) + relu + conv2
//        + relu + FC partial + deterministic last-CTA-per-graph reduction
// ---------------------------------------------------------------------------
__global__ __launch_bounds__(256, 2) void conv_kernel(
    const int*   __restrict__ recep,
    const float* __restrict__ nf,
    const float* __restrict__ b1,
    const float* __restrict__ w2,
    const float* __restrict__ b2,
    const float* __restrict__ fcw,
    const float* __restrict__ fcb,
    float*       __restrict__ out)
{
    extern __shared__ char smem[];
    __shared__ int   sfin[2];
    __shared__ float sred[256];
    const uint32_t sbase = smem_u32(smem);
    int* sIdx = (int*)(smem + SMB_IDX);
    const int tid  = threadIdx.x;
    const int wid  = tid >> 5;
    const int lane = tid & 31;
    const int m0   = blockIdx.x * MTILE;
    const int fr   = lane >> 2;      // 0..7
    const int fc   = lane & 3;       // 0..3

    // node BYTE-offset table: 128 rows x 10 neighbors
    for (int i = tid; i < MTILE * NB; i += 256) {
        int row = i / NB;
        int k   = i - row * NB;
        int m   = m0 + row;
        int b   = m / SEQ;
        int s   = m - b * SEQ;
        sIdx[i] = (recep[b * NNODE + s * NB + k] + b * NNODE) * (DF * 4);
    }
    __syncthreads();

    const char* nfb  = (const char*)nf;
    const int   arow = tid >> 1;              // this thread's row, all stages
    const int   qh   = (tid & 1) * 8;         // float4 half of the row
    const int   swp  = (arow & 7) << 1;       // store swizzle
    const uint32_t adst0 = sbase + SMB_A + (uint32_t)arow * 256u;

    // stage s: k = s>>1, half h = s&1 (64 K-cols), buffer bi = s&1
    auto prefetch = [&](int s) {
        const int k = s >> 1, h = s & 1, bi = s & 1;
        const char* src = nfb + sIdx[arow * NB + k] + h * 256 + qh * 16;
        const uint32_t dbase = adst0 + (uint32_t)(bi * A_STAGE);
#pragma unroll
        for (int j = 0; j < 8; j++)
            cp16(dbase + (uint32_t)(((qh + j) ^ swp) * 16), src + j * 16);
        CP_COMMIT();
    };

    prefetch(0);
    prefetch(1);

    float acc[4][4];
#pragma unroll
    for (int nt = 0; nt < 4; nt++)
#pragma unroll
        for (int j = 0; j < 4; j++) acc[nt][j] = 0.f;

    const int row0 = wid * 16 + fr;
    const int sw   = fr << 1;
    const int oi   = (fc & 1) * 2;

    for (int s = 0; s < NSTAGE; s++) {
        const int bi = s & 1;
        if (s < NSTAGE - 1) CP_WAIT(1); else CP_WAIT(0);
        __syncthreads();

        const float*    aw  = (const float*)(smem + SMB_A + bi * A_STAGE);
        const uint32_t* bwk = g_w1h + (s >> 1) * 2048 + (s & 1) * 1024;  // L1-hot
#pragma unroll
        for (int t = 0; t < 4; t++) {
            const int q0 = (4 * t + (fc >> 1)) ^ sw;       // cols 16t+2fc
            const int q1 = (4 * t + 2 + (fc >> 1)) ^ sw;   // cols 16t+8+2fc
            float2 v00 = *(const float2*)(aw + row0 * 64       + q0 * 4 + oi);
            float2 v10 = *(const float2*)(aw + (row0 + 8) * 64 + q0 * 4 + oi);
            float2 v01 = *(const float2*)(aw + row0 * 64       + q1 * 4 + oi);
            float2 v11 = *(const float2*)(aw + (row0 + 8) * 64 + q1 * 4 + oi);
            uint32_t a0 = packh2(v00), a1 = packh2(v10);
            uint32_t a2 = packh2(v01), a3 = packh2(v11);
            const int p0 = (8 * t + fc) * 32;          // k = 16t+2fc,+1
            const int p1 = (8 * t + 4 + fc) * 32;      // k = 16t+8+2fc,+1
#pragma unroll
            for (int nt = 0; nt < 4; nt++) {
                uint32_t b0  = __ldg(bwk + p0 + nt * 8 + fr);
                uint32_t b1v = __ldg(bwk + p1 + nt * 8 + fr);
                mma16816(acc[nt], a0, a1, a2, a3, b0, b1v);
            }
        }
        __syncthreads();                            // done reading stage bi
        if (s + 2 < NSTAGE) prefetch(s + 2);        // refill freed buffer
    }

    // y1 = relu(conv1 + b1) -> smem [128][33]; w2 -> smem (buffer 1 region)
    float* y1s = (float*)(smem + SMB_A);
    float* w2s = (float*)(smem + SMB_A + A_STAGE);
    const int rb = wid * 16;
#pragma unroll
    for (int nt = 0; nt < 4; nt++) {
        int col = nt * 8 + 2 * fc;
        float bc0 = __ldg(b1 + col), bc1 = __ldg(b1 + col + 1);
        y1s[(rb + fr)     * 33 + col]     = fmaxf(acc[nt][0] + bc0, 0.f);
        y1s[(rb + fr)     * 33 + col + 1] = fmaxf(acc[nt][1] + bc1, 0.f);
        y1s[(rb + fr + 8) * 33 + col]     = fmaxf(acc[nt][2] + bc0, 0.f);
        y1s[(rb + fr + 8) * 33 + col + 1] = fmaxf(acc[nt][3] + bc1, 0.f);
    }
    ((float4*)w2s)[tid] = ((const float4*)w2)[tid & 255];
    __syncthreads();

    // conv2 (fp32) + relu + FC partial: one thread per row
    if (tid < MTILE) {
        int m = m0 + tid;
        int b = m / SEQ;
        int s = m - b * SEQ;
        const float* yr = y1s + tid * 33;
        float p = 0.f;
#pragma unroll
        for (int c2 = 0; c2 < C2; c2++) {
            float v = __ldg(b2 + c2);
            const float* wv = w2s + c2 * 32;
#pragma unroll
            for (int q = 0; q < 32; q += 4) {
                v = fmaf(wv[q],     yr[q],     v);
                v = fmaf(wv[q + 1], yr[q + 1], v);
                v = fmaf(wv[q + 2], yr[q + 2], v);
                v = fmaf(wv[q + 3], yr[q + 3], v);
            }
            v = fmaxf(v, 0.f);
            p = fmaf(v, __ldg(fcw + c2 * SEQ + s), p);
        }
        g_partial[m] = p;
        __threadfence();
    }
    __syncthreads();

    // --- deterministic final reduction: last CTA to finish a graph sums it
    if (tid == 0) {
        int bA = m0 / SEQ;
        int bB = (m0 + MTILE - 1) / SEQ;
        sfin[0] = -1; sfin[1] = -1;
#pragma unroll 2
        for (int j = 0; j < 2; j++) {
            int b = bA + j;
            if (b > bB) break;
            int lo = max(b * SEQ, m0);
            int hi = min((b + 1) * SEQ, m0 + MTILE);
            int my = hi - lo;
            int old = atomicAdd(&g_cnt[b], my);
            if (old + my == SEQ) sfin[j] = b;
        }
    }
    __syncthreads();

#pragma unroll 2
    for (int j = 0; j < 2; j++) {
        int b = sfin[j];
        if (b < 0) continue;
        __threadfence();                     // acquire other CTAs' partials
        float s = 0.f;
        for (int i = tid; i < SEQ; i += 256) s += g_partial[b * SEQ + i];
        sred[tid] = s;
        __syncthreads();
        for (int st = 128; st > 0; st >>= 1) {
            if (tid < st) sred[tid] += sred[tid + st];
            __syncthreads();
        }
        if (tid == 0) {
            out[b] = sred[0] + __ldg(fcb);
            g_cnt[b] = 0;                    // reset for graph replay
        }
        __syncthreads();
    }
}

// ---------------------------------------------------------------------------
extern "C" void kernel_launch(void* const* d_in, const int* in_sizes, int n_in,
                              void* d_out, int out_size) {
    const int*   recep = (const int*)  d_in[0];
    const float* nf    = (const float*)d_in[1];
    const float* w1    = (const float*)d_in[2];
    const float* b1    = (const float*)d_in[3];
    const float* w2    = (const float*)d_in[4];
    const float* b2    = (const float*)d_in[5];
    const float* fcw   = (const float*)d_in[6];
    const float* fcb   = (const float*)d_in[7];
    float* out = (float*)d_out;

    cudaFuncSetAttribute(conv_kernel, cudaFuncAttributeMaxDynamicSharedMemorySize, SMB_TOTAL);
    prep_kernel<<<(NB*DF*C1 + 255) / 256, 256>>>(w1);
    conv_kernel<<<NCTA, 256, SMB_TOTAL>>>(recep, nf, b1, w2, b2, fcw, fcb, out);
}

// round 12
// speedup vs baseline: 3.5284x; 3.1291x over previous
#include <cuda_runtime.h>
#include <cuda_fp16.h>
#include <cstdint>

#define BSZ   128
#define NNODE 4000
#define DF    128
#define NB    10
#define SEQ   400
#define C1    32
#define C2    32
#define MTILE 128
#define MTOT  (BSZ*SEQ)          // 51200
#define NCTA  (MTOT/MTILE)       // 400
#define NSTAGE 20                // NB * 2 half-K stages

// ---- shared memory byte layout (dynamic) ----------------------------------
#define SMB_IDX   0                         // 1280 u16 recep values = 2560 B
#define SMB_A     2560                      // 2 x 32 KB fp32 half-K stages
#define A_STAGE   (MTILE*64*4)              // 32768
#define SMB_B     (SMB_A + 2*A_STAGE)       // 68096
#define B_STAGE   4096                      // dense 32 pair-rows x 128 B, swizzled
#define SMB_TOTAL (SMB_B + 2*B_STAGE)       // 76288 -> 3 CTAs/SM

__device__ uint32_t g_w1h[NB*64*32];  // dense f16 pairs: [k][pair(d/2)][c1]
__device__ float    g_partial[MTOT];
__device__ int      g_cnt[BSZ];       // zero-init; self-resetting per call

__device__ __forceinline__ uint32_t smem_u32(const void* p) {
    uint32_t a;
    asm("{ .reg .u64 t; cvta.to.shared.u64 t, %1; cvt.u32.u64 %0, t; }" : "=r"(a) : "l"(p));
    return a;
}
__device__ __forceinline__ void cp16(uint32_t dst, const void* src) {
    asm volatile("cp.async.cg.shared.global [%0], [%1], 16;" :: "r"(dst), "l"(src));
}
#define CP_COMMIT() asm volatile("cp.async.commit_group;" ::: "memory")
#define CP_WAIT(N)  asm volatile("cp.async.wait_group %0;" :: "n"(N) : "memory")

__device__ __forceinline__ uint32_t packh2(float2 v) {
    uint32_t r;
    asm("cvt.rn.f16x2.f32 %0, %1, %2;" : "=r"(r) : "f"(v.y), "f"(v.x));
    return r;
}
__device__ __forceinline__ void mma16816(float* c, uint32_t a0, uint32_t a1,
                                         uint32_t a2, uint32_t a3,
                                         uint32_t b0, uint32_t b1) {
    asm volatile(
        "mma.sync.aligned.m16n8k16.row.col.f32.f16.f16.f32 "
        "{%0,%1,%2,%3}, {%4,%5,%6,%7}, {%8,%9}, {%0,%1,%2,%3};"
        : "+f"(c[0]), "+f"(c[1]), "+f"(c[2]), "+f"(c[3])
        : "r"(a0), "r"(a1), "r"(a2), "r"(a3), "r"(b0), "r"(b1));
}

// ---------------------------------------------------------------------------
// prep: conv1 weights -> dense f16 pair-interleaved [k][d/2][c1]
// ---------------------------------------------------------------------------
__global__ void prep_kernel(const float* __restrict__ w1) {
    int i = blockIdx.x * blockDim.x + threadIdx.x;     // 40960
    if (i >= NB * DF * C1) return;
    int k   = i >> 12;
    int rem = i & 4095;
    int d   = rem >> 5;
    int c1  = rem & 31;
    float v = w1[c1 * (DF * NB) + d * NB + k];
    ((__half*)g_w1h)[((size_t)k * 2048 + (d >> 1) * 32 + c1) * 2 + (d & 1)] =
        __float2half_rn(v);
}

// ---------------------------------------------------------------------------
// fused: R6-shape cp.async pipeline + f16 mma conv1 + relu + conv2 + relu
//        + FC partial + deterministic last-CTA-per-graph reduction
// ---------------------------------------------------------------------------
__global__ __launch_bounds__(256, 3) void conv_kernel(
    const int*   __restrict__ recep,
    const float* __restrict__ nf,
    const float* __restrict__ b1,
    const float* __restrict__ w2,
    const float* __restrict__ b2,
    const float* __restrict__ fcw,
    const float* __restrict__ fcb,
    float*       __restrict__ out)
{
    extern __shared__ char smem[];
    const uint32_t sbase = smem_u32(smem);
    uint16_t* sIdx16 = (uint16_t*)(smem + SMB_IDX);
    const int tid  = threadIdx.x;
    const int wid  = tid >> 5;
    const int lane = tid & 31;
    const int m0   = blockIdx.x * MTILE;
    const int fr   = lane >> 2;      // 0..7
    const int fc   = lane & 3;       // 0..3

    // u16 recep table: 128 rows x 10 neighbors
    for (int i = tid; i < MTILE * NB; i += 256) {
        int row = i / NB;
        int k   = i - row * NB;
        int m   = m0 + row;
        int b   = m / SEQ;
        int s   = m - b * SEQ;
        sIdx16[i] = (uint16_t)recep[b * NNODE + s * NB + k];
    }
    __syncthreads();

    // per-thread gather constants (R6 pattern: slot = tid + j*256)
    const int rbase = tid >> 4;               // row for j=0; rows rbase + 16j
    const int q     = tid & 15;               // float4 index within row-half
    uint32_t rowbase8[8];                     // graph base byte offsets
#pragma unroll
    for (int j = 0; j < 8; j++) {
        int m = m0 + rbase + j * 16;
        rowbase8[j] = (uint32_t)(m / SEQ) * (NNODE * DF * 4);
    }
    const uint32_t adst = sbase + SMB_A + (uint32_t)rbase * 256u +
                          (uint32_t)((q ^ ((rbase & 7) << 1)) * 16);
    const char* nfq = (const char*)nf + q * 16;

    // stage s: k = s>>1, half h = s&1 (64 K-cols), buffer bi = s&1
    auto prefetch = [&](int s) {
        const int k = s >> 1, h = s & 1, bi = s & 1;
        const char* src0 = nfq + h * 256;
        const int io = rbase * NB + k;
        const uint32_t d0 = adst + (uint32_t)(bi * A_STAGE);
#pragma unroll
        for (int j = 0; j < 8; j++) {
            uint32_t off = (uint32_t)sIdx16[io + j * 160] * 512u + rowbase8[j];
            cp16(d0 + (uint32_t)(j * 4096), src0 + off);
        }
        // B: dense swizzled 4 KB (one cp16 per thread)
        {
            int row = tid >> 3, c4 = tid & 7;
            int c4p = c4 ^ ((row & 3) << 1);
            cp16(sbase + SMB_B + (uint32_t)(bi * B_STAGE) +
                     (uint32_t)(row * 128 + c4p * 16),
                 (const char*)g_w1h + (size_t)k * 8192 + h * 4096 + tid * 16);
        }
        CP_COMMIT();
    };

    prefetch(0);
    prefetch(1);

    float acc[4][4];
#pragma unroll
    for (int nt = 0; nt < 4; nt++)
#pragma unroll
        for (int j = 0; j < 4; j++) acc[nt][j] = 0.f;

    const int row0 = wid * 16 + fr;
    const int sw   = fr << 1;
    const int oi   = (fc & 1) * 2;
    const int bxor = fc << 3;                 // B column swizzle for this lane

    for (int s = 0; s < NSTAGE; s++) {
        const int bi = s & 1;
        if (s < NSTAGE - 1) CP_WAIT(1); else CP_WAIT(0);
        __syncthreads();

        const float*    aw = (const float*)(smem + SMB_A + bi * A_STAGE);
        const uint32_t* bw = (const uint32_t*)(smem + SMB_B + bi * B_STAGE);
#pragma unroll
        for (int t = 0; t < 4; t++) {
            const int q0 = (4 * t + (fc >> 1)) ^ sw;       // cols 16t+2fc
            const int q1 = (4 * t + 2 + (fc >> 1)) ^ sw;   // cols 16t+8+2fc
            float2 v00 = *(const float2*)(aw + row0 * 64       + q0 * 4 + oi);
            float2 v10 = *(const float2*)(aw + (row0 + 8) * 64 + q0 * 4 + oi);
            float2 v01 = *(const float2*)(aw + row0 * 64       + q1 * 4 + oi);
            float2 v11 = *(const float2*)(aw + (row0 + 8) * 64 + q1 * 4 + oi);
            uint32_t a0 = packh2(v00), a1 = packh2(v10);
            uint32_t a2 = packh2(v01), a3 = packh2(v11);
            const int p0 = (8 * t + fc) * 32;          // pair-row k = 16t+2fc
            const int p1 = (8 * t + 4 + fc) * 32;      // pair-row k = 16t+8+2fc
#pragma unroll
            for (int nt = 0; nt < 4; nt++) {
                const int col = (nt * 8 + fr) ^ bxor;
                uint32_t b0  = bw[p0 + col];
                uint32_t b1v = bw[p1 + col];
                mma16816(acc[nt], a0, a1, a2, a3, b0, b1v);
            }
        }
        __syncthreads();                            // done reading stage bi
        if (s + 2 < NSTAGE) prefetch(s + 2);        // refill freed buffer
    }

    // y1 = relu(conv1 + b1) -> smem [128][33]; w2 -> stage-1 A region
    float* y1s = (float*)(smem + SMB_A);
    float* w2s = (float*)(smem + SMB_A + A_STAGE);
    const int rb = wid * 16;
#pragma unroll
    for (int nt = 0; nt < 4; nt++) {
        int col = nt * 8 + 2 * fc;
        float bc0 = __ldg(b1 + col), bc1 = __ldg(b1 + col + 1);
        y1s[(rb + fr)     * 33 + col]     = fmaxf(acc[nt][0] + bc0, 0.f);
        y1s[(rb + fr)     * 33 + col + 1] = fmaxf(acc[nt][1] + bc1, 0.f);
        y1s[(rb + fr + 8) * 33 + col]     = fmaxf(acc[nt][2] + bc0, 0.f);
        y1s[(rb + fr + 8) * 33 + col + 1] = fmaxf(acc[nt][3] + bc1, 0.f);
    }
    ((float4*)w2s)[tid] = ((const float4*)w2)[tid & 255];
    __syncthreads();

    // conv2 (fp32) + relu + FC partial: one thread per row
    if (tid < MTILE) {
        int m = m0 + tid;
        int b = m / SEQ;
        int s = m - b * SEQ;
        const float* yr = y1s + tid * 33;
        float p = 0.f;
#pragma unroll
        for (int c2 = 0; c2 < C2; c2++) {
            float v = __ldg(b2 + c2);
            const float* wv = w2s + c2 * 32;
#pragma unroll
            for (int qq = 0; qq < 32; qq += 4) {
                v = fmaf(wv[qq],     yr[qq],     v);
                v = fmaf(wv[qq + 1], yr[qq + 1], v);
                v = fmaf(wv[qq + 2], yr[qq + 2], v);
                v = fmaf(wv[qq + 3], yr[qq + 3], v);
            }
            v = fmaxf(v, 0.f);
            p = fmaf(v, __ldg(fcw + c2 * SEQ + s), p);
        }
        g_partial[m] = p;
        __threadfence();
    }
    __syncthreads();

    // --- deterministic final reduction: last CTA to finish a graph sums it
    int*   sfin = (int*)(smem + SMB_B + B_STAGE);      // reuse B stage-1 region
    float* sred = (float*)(smem + SMB_B);              // reuse B stage-0 region
    if (tid == 0) {
        int bA = m0 / SEQ;
        int bB = (m0 + MTILE - 1) / SEQ;
        sfin[0] = -1; sfin[1] = -1;
#pragma unroll 2
        for (int j = 0; j < 2; j++) {
            int b = bA + j;
            if (b > bB) break;
            int lo = max(b * SEQ, m0);
            int hi = min((b + 1) * SEQ, m0 + MTILE);
            int my = hi - lo;
            int old = atomicAdd(&g_cnt[b], my);
            if (old + my == SEQ) sfin[j] = b;
        }
    }
    __syncthreads();

#pragma unroll 2
    for (int j = 0; j < 2; j++) {
        int b = sfin[j];
        if (b < 0) continue;
        __threadfence();                     // acquire other CTAs' partials
        float s = 0.f;
        for (int i = tid; i < SEQ; i += 256) s += g_partial[b * SEQ + i];
        sred[tid] = s;
        __syncthreads();
        for (int st = 128; st > 0; st >>= 1) {
            if (tid < st) sred[tid] += sred[tid + st];
            __syncthreads();
        }
        if (tid == 0) {
            out[b] = sred[0] + __ldg(fcb);
            g_cnt[b] = 0;                    // reset for graph replay
        }
        __syncthreads();
    }
}

// ---------------------------------------------------------------------------
extern "C" void kernel_launch(void* const* d_in, const int* in_sizes, int n_in,
                              void* d_out, int out_size) {
    const int*   recep = (const int*)  d_in[0];
    const float* nf    = (const float*)d_in[1];
    const float* w1    = (const float*)d_in[2];
    const float* b1    = (const float*)d_in[3];
    const float* w2    = (const float*)d_in[4];
    const float* b2    = (const float*)d_in[5];
    const float* fcw   = (const float*)d_in[6];
    const float* fcb   = (const float*)d_in[7];
    float* out = (float*)d_out;

    cudaFuncSetAttribute(conv_kernel, cudaFuncAttributeMaxDynamicSharedMemorySize, SMB_TOTAL);
    prep_kernel<<<(NB*DF*C1 + 255) / 256, 256>>>(w1);
    conv_kernel<<<NCTA, 256, SMB_TOTAL>>>(recep, nf, b1, w2, b2, fcw, fcb, out);
}